// round 1
// baseline (speedup 1.0000x reference)
#include <cuda_runtime.h>
#include <math.h>

#define B_  2
#define T_  1024
#define E_  1024
#define H_  16
#define HD_ 64
#define FF_ 4096
#define L_  8
#define V_  50257
#define M_  (B_*T_)   // 2048

// ---------------- scratch (device globals; no allocation allowed) ----------
__device__ float g_x   [M_*E_];
__device__ float g_x0  [M_*E_];
__device__ float g_h   [M_*E_];
__device__ float g_qkv [M_*3*E_];
__device__ float g_q   [M_*E_];   // [B,H,T,HD]
__device__ float g_k   [M_*E_];
__device__ float g_v   [M_*E_];
__device__ float g_o   [M_*E_];   // [B,T,E]
__device__ float g_gate[M_*H_];
__device__ float g_g   [M_*FF_];
__device__ float g_u   [M_*FF_];

// ---------------- embedding ------------------------------------------------
__global__ void embed_kernel(const int* __restrict__ idx,
                             const float* __restrict__ tok) {
    int i = blockIdx.x * 256 + threadIdx.x;       // < M_*E_
    int bt = i >> 10;
    int e  = i & (E_ - 1);
    float v = tok[(size_t)idx[bt] * E_ + e];
    g_x[i]  = v;
    g_x0[i] = v;
}

// ---------------- rmsnorm ---------------------------------------------------
__global__ void rmsnorm_kernel(const float* __restrict__ x,
                               const float* __restrict__ w,
                               float* __restrict__ out) {
    __shared__ float red[256];
    int row = blockIdx.x;
    const float* xr = x + (size_t)row * E_;
    float s = 0.f;
    for (int e = threadIdx.x; e < E_; e += 256) { float v = xr[e]; s += v * v; }
    red[threadIdx.x] = s;
    __syncthreads();
    for (int o = 128; o > 0; o >>= 1) {
        if (threadIdx.x < o) red[threadIdx.x] += red[threadIdx.x + o];
        __syncthreads();
    }
    float norm = rsqrtf(red[0] * (1.f / E_) + 1e-6f);
    for (int e = threadIdx.x; e < E_; e += 256)
        out[(size_t)row * E_ + e] = xr[e] * norm * w[e];
}

// ---------------- ve gate (odd layers) -------------------------------------
__global__ void gate_kernel(const float* __restrict__ hn,
                            const float* __restrict__ vgw) {
    int i = blockIdx.x * 256 + threadIdx.x;       // < M_*H_
    if (i >= M_ * H_) return;
    int bt = i / H_, h = i % H_;
    const float* hr = hn + (size_t)bt * E_;
    const float* wr = vgw + h * 32;
    float s = 0.f;
#pragma unroll
    for (int c = 0; c < 32; c++) s = fmaf(hr[c], wr[c], s);
    g_gate[i] = 2.f / (1.f + expf(-s));
}

// ---------------- rope + head split (+ ve add) ------------------------------
__global__ void rope_split_kernel(const float* __restrict__ qkv, int has_gate) {
    int bt = blockIdx.x;
    int b = bt / T_, t = bt % T_;
    const float* src = qkv + (size_t)bt * 3 * E_;
    float tf = (float)t;

#pragma unroll
    for (int which = 0; which < 2; ++which) {
        const float* sp = src + which * E_;
        float* dst = (which == 0) ? g_q : g_k;
        for (int item = threadIdx.x; item < H_ * 32; item += blockDim.x) {
            int h = item >> 5, p = item & 31;
            int d0 = 2 * p, d1 = 2 * p + 1;
            // cos/sin tables: index d uses freq[d & 31] (concatenated halves)
            float ang0 = tf * powf(10000.f, -(float)(d0 & 31) * (1.f / 32.f));
            float ang1 = tf * powf(10000.f, -(float)(d1 & 31) * (1.f / 32.f));
            float s0, c0, s1, c1;
            sincosf(ang0, &s0, &c0);
            sincosf(ang1, &s1, &c1);
            float x0v = sp[h * HD_ + d0];
            float x1v = sp[h * HD_ + d1];
            // rotate: rot[2i] = -x[2i+1], rot[2i+1] = x[2i]
            float o0 = x0v * c0 - x1v * s0;
            float o1 = x1v * c1 + x0v * s1;
            size_t base = ((size_t)(b * H_ + h) * T_ + t) * HD_;
            dst[base + d0] = o0;
            dst[base + d1] = o1;
        }
    }
    // v (+ gated value-embedding for odd layers)
    for (int item = threadIdx.x; item < E_; item += blockDim.x) {
        int h = item >> 6, d = item & 63;
        float vv = src[2 * E_ + item];
        if (has_gate)
            vv += g_gate[bt * H_ + h] * g_x0[(size_t)bt * E_ + item];
        g_v[((size_t)(b * H_ + h) * T_ + t) * HD_ + d] = vv;
    }
}

// ---------------- causal attention (fp32 flash-style) ----------------------
__global__ __launch_bounds__(128) void attn_kernel() {
    __shared__ float Ks[64][64];
    __shared__ float Vs[64][64];
    int bh = blockIdx.y;
    int qi = blockIdx.x * 128 + threadIdx.x;      // global query index < T_
    const float* qp = g_q + ((size_t)bh * T_ + qi) * HD_;

    float q[64], o[64];
#pragma unroll
    for (int d4 = 0; d4 < 16; d4++) {
        float4 v = ((const float4*)qp)[d4];
        q[4*d4] = v.x; q[4*d4+1] = v.y; q[4*d4+2] = v.z; q[4*d4+3] = v.w;
    }
#pragma unroll
    for (int d = 0; d < 64; d++) o[d] = 0.f;
    float m = -1e30f, l = 0.f;

    int ntiles = blockIdx.x * 2 + 2;              // key tiles of 64 up to q-tile end
    for (int kt = 0; kt < ntiles; kt++) {
        const float* kp = g_k + ((size_t)bh * T_ + kt * 64) * HD_;
        const float* vp = g_v + ((size_t)bh * T_ + kt * 64) * HD_;
        __syncthreads();
        for (int f = threadIdx.x; f < 64 * 16; f += 128) {
            int r = f >> 4, c4 = f & 15;
            ((float4*)&Ks[r][0])[c4] = ((const float4*)(kp + r * 64))[c4];
            ((float4*)&Vs[r][0])[c4] = ((const float4*)(vp + r * 64))[c4];
        }
        __syncthreads();
        int jmax = qi - kt * 64 + 1;
        if (jmax > 64) jmax = 64;
        for (int j = 0; j < jmax; j++) {
            float s = 0.f;
            const float4* kr = (const float4*)&Ks[j][0];
#pragma unroll
            for (int d4 = 0; d4 < 16; d4++) {
                float4 kk = kr[d4];
                s = fmaf(q[4*d4],   kk.x, s);
                s = fmaf(q[4*d4+1], kk.y, s);
                s = fmaf(q[4*d4+2], kk.z, s);
                s = fmaf(q[4*d4+3], kk.w, s);
            }
            s *= 0.125f;                           // 1/sqrt(64)
            float mn   = fmaxf(m, s);
            float corr = __expf(m - mn);
            float p    = __expf(s - mn);
            l = l * corr + p;
            m = mn;
            const float4* vr = (const float4*)&Vs[j][0];
#pragma unroll
            for (int d4 = 0; d4 < 16; d4++) {
                float4 vv = vr[d4];
                o[4*d4]   = fmaf(p, vv.x, o[4*d4]   * corr);
                o[4*d4+1] = fmaf(p, vv.y, o[4*d4+1] * corr);
                o[4*d4+2] = fmaf(p, vv.z, o[4*d4+2] * corr);
                o[4*d4+3] = fmaf(p, vv.w, o[4*d4+3] * corr);
            }
        }
    }
    float inv = 1.f / l;
    int b = bh / H_, h = bh % H_;
    float* op = g_o + ((size_t)(b * T_ + qi)) * E_ + h * HD_;
#pragma unroll
    for (int d4 = 0; d4 < 16; d4++) {
        float4 vv = make_float4(o[4*d4] * inv, o[4*d4+1] * inv,
                                o[4*d4+2] * inv, o[4*d4+3] * inv);
        ((float4*)op)[d4] = vv;
    }
}

// ---------------- swiglu ----------------------------------------------------
__global__ void swiglu_kernel() {
    size_t i = (size_t)blockIdx.x * 256 + threadIdx.x;   // < M_*FF_
    float gv = g_g[i];
    float s = gv / (1.f + expf(-gv));
    g_g[i] = s * g_u[i];
}

// ---------------- generic NT GEMM: C[M,N] (op)= A[M,K] * B[N,K]^T ----------
enum { EP_NONE = 0, EP_ADD = 1, EP_TANH = 2 };

template <int EPI>
__global__ __launch_bounds__(256) void gemm_nt(const float* __restrict__ A,
                                               const float* __restrict__ Bm,
                                               float* __restrict__ C,
                                               int M, int N, int K) {
    __shared__ float As[16][128];
    __shared__ float Bs[16][128];
    const int tid  = threadIdx.x;
    const int brow = blockIdx.y * 128;
    const int bcol = blockIdx.x * 128;
    const int tx = tid & 15, ty = tid >> 4;
    const int lrow = tid >> 2, lc4 = tid & 3;

    float acc[8][8];
#pragma unroll
    for (int i = 0; i < 8; i++)
#pragma unroll
        for (int j = 0; j < 8; j++) acc[i][j] = 0.f;

    for (int k0 = 0; k0 < K; k0 += 16) {
#pragma unroll
        for (int half = 0; half < 2; half++) {
            int r = lrow + half * 64;
            int gr = brow + r;
            float4 av = make_float4(0.f, 0.f, 0.f, 0.f);
            if (gr < M) av = *(const float4*)(A + (size_t)gr * K + k0 + lc4 * 4);
            As[lc4*4+0][r] = av.x; As[lc4*4+1][r] = av.y;
            As[lc4*4+2][r] = av.z; As[lc4*4+3][r] = av.w;
            int gc = bcol + r;
            float4 bv = make_float4(0.f, 0.f, 0.f, 0.f);
            if (gc < N) bv = *(const float4*)(Bm + (size_t)gc * K + k0 + lc4 * 4);
            Bs[lc4*4+0][r] = bv.x; Bs[lc4*4+1][r] = bv.y;
            Bs[lc4*4+2][r] = bv.z; Bs[lc4*4+3][r] = bv.w;
        }
        __syncthreads();
#pragma unroll
        for (int k = 0; k < 16; k++) {
            float4 a0 = *(const float4*)&As[k][ty * 8];
            float4 a1 = *(const float4*)&As[k][ty * 8 + 4];
            float4 b0 = *(const float4*)&Bs[k][tx * 8];
            float4 b1 = *(const float4*)&Bs[k][tx * 8 + 4];
            float a[8] = {a0.x, a0.y, a0.z, a0.w, a1.x, a1.y, a1.z, a1.w};
            float b[8] = {b0.x, b0.y, b0.z, b0.w, b1.x, b1.y, b1.z, b1.w};
#pragma unroll
            for (int i = 0; i < 8; i++)
#pragma unroll
                for (int j = 0; j < 8; j++)
                    acc[i][j] = fmaf(a[i], b[j], acc[i][j]);
        }
        __syncthreads();
    }
#pragma unroll
    for (int i = 0; i < 8; i++) {
        int gr = brow + ty * 8 + i;
        if (gr >= M) continue;
#pragma unroll
        for (int j = 0; j < 8; j++) {
            int gc = bcol + tx * 8 + j;
            if (gc >= N) continue;
            size_t off = (size_t)gr * N + gc;
            float v = acc[i][j];
            if (EPI == EP_ADD)  v += C[off];
            if (EPI == EP_TANH) v = 30.f * tanhf(v * (1.f / 30.f));
            C[off] = v;
        }
    }
}

// ---------------- launch ----------------------------------------------------
extern "C" void kernel_launch(void* const* d_in, const int* in_sizes, int n_in,
                              void* d_out, int out_size) {
    const int*   idx  = (const int*)  d_in[0];
    const float* tok  = (const float*)d_in[1];
    const float* ln1  = (const float*)d_in[2];
    const float* qkvw = (const float*)d_in[3];
    const float* outw = (const float*)d_in[4];
    const float* vgw  = (const float*)d_in[5];
    const float* ln2  = (const float*)d_in[6];
    const float* wgw  = (const float*)d_in[7];
    const float* wuw  = (const float*)d_in[8];
    const float* wdw  = (const float*)d_in[9];
    const float* lnf  = (const float*)d_in[10];
    float* out = (float*)d_out;

    float *x, *h, *qkv, *ob, *gb, *ub;
    cudaGetSymbolAddress((void**)&x,   g_x);
    cudaGetSymbolAddress((void**)&h,   g_h);
    cudaGetSymbolAddress((void**)&qkv, g_qkv);
    cudaGetSymbolAddress((void**)&ob,  g_o);
    cudaGetSymbolAddress((void**)&gb,  g_g);
    cudaGetSymbolAddress((void**)&ub,  g_u);

    embed_kernel<<<(M_ * E_) / 256, 256>>>(idx, tok);

    for (int i = 0; i < L_; i++) {
        rmsnorm_kernel<<<M_, 256>>>(x, ln1 + i * E_, h);
        gemm_nt<EP_NONE><<<dim3(3 * E_ / 128, M_ / 128), 256>>>(
            h, qkvw + (size_t)i * 3 * E_ * E_, qkv, M_, 3 * E_, E_);
        if (i & 1)
            gate_kernel<<<(M_ * H_ + 255) / 256, 256>>>(h, vgw + (size_t)i * H_ * 32);
        rope_split_kernel<<<M_, 256>>>(qkv, i & 1);
        attn_kernel<<<dim3(T_ / 128, B_ * H_), 128>>>();
        gemm_nt<EP_ADD><<<dim3(E_ / 128, M_ / 128), 256>>>(
            ob, outw + (size_t)i * E_ * E_, x, M_, E_, E_);

        rmsnorm_kernel<<<M_, 256>>>(x, ln2 + i * E_, h);
        gemm_nt<EP_NONE><<<dim3(FF_ / 128, M_ / 128), 256>>>(
            h, wgw + (size_t)i * FF_ * E_, gb, M_, FF_, E_);
        gemm_nt<EP_NONE><<<dim3(FF_ / 128, M_ / 128), 256>>>(
            h, wuw + (size_t)i * FF_ * E_, ub, M_, FF_, E_);
        swiglu_kernel<<<(M_ * FF_) / 256, 256>>>();
        gemm_nt<EP_ADD><<<dim3(E_ / 128, M_ / 128), 256>>>(
            gb, wdw + (size_t)i * E_ * FF_, x, M_, E_, FF_);
    }

    rmsnorm_kernel<<<M_, 256>>>(x, lnf, h);
    gemm_nt<EP_TANH><<<dim3((V_ + 127) / 128, M_ / 128), 256>>>(
        h, tok, out, M_, V_, E_);
}

// round 3
// speedup vs baseline: 1.6675x; 1.6675x over previous
#include <cuda_runtime.h>
#include <cuda_bf16.h>
#include <mma.h>
#include <math.h>
#include <stdint.h>

using namespace nvcuda;

#define B_  2
#define T_  1024
#define E_  1024
#define H_  16
#define HD_ 64
#define FF_ 4096
#define L_  8
#define V_  50257
#define M_  (B_*T_)   // 2048

// ===================== scratch (device globals) =====================
__device__ float g_x   [M_*E_];
__device__ float g_x0  [M_*E_];
__device__ float g_h   [M_*E_];
__device__ float g_qkv [M_*3*E_];
__device__ float g_q   [M_*E_];
__device__ float g_k   [M_*E_];
__device__ float g_v   [M_*E_];
__device__ float g_o   [M_*E_];
__device__ float g_gate[M_*H_];
__device__ float g_g   [M_*FF_];
__device__ float g_u   [M_*FF_];

// bf16 split buffers (hi/lo 3K layout along K)
__device__ __nv_bfloat16 g_qkvw3[(size_t)L_*3*E_*3*E_];
__device__ __nv_bfloat16 g_outw3[(size_t)L_*E_*3*E_];
__device__ __nv_bfloat16 g_wg3  [(size_t)L_*FF_*3*E_];
__device__ __nv_bfloat16 g_wu3  [(size_t)L_*FF_*3*E_];
__device__ __nv_bfloat16 g_wd3  [(size_t)L_*E_*3*FF_];
__device__ __nv_bfloat16 g_tok3 [(size_t)V_*3*E_];
__device__ __nv_bfloat16 g_a3s  [(size_t)M_*3*E_];
__device__ __nv_bfloat16 g_a3b  [(size_t)M_*3*FF_];

// ===================== split conversions =====================
// A role: [hi | hi | lo]
__global__ void cvt_a3(const float* __restrict__ src, __nv_bfloat16* __restrict__ dst, int K) {
    size_t i = (size_t)blockIdx.x * 256 + threadIdx.x;
    size_t m = i / (size_t)K;
    int k = (int)(i - m * K);
    float f = src[i];
    __nv_bfloat16 hi = __float2bfloat16(f);
    __nv_bfloat16 lo = __float2bfloat16(f - __bfloat162float(hi));
    size_t base = m * (size_t)(3 * K);
    dst[base + k]         = hi;
    dst[base + K + k]     = hi;
    dst[base + 2 * K + k] = lo;
}

// B role: [hi | lo | hi]
__global__ void cvt_b3(const float* __restrict__ src, __nv_bfloat16* __restrict__ dst,
                       int K, size_t total) {
    size_t i = (size_t)blockIdx.x * 256 + threadIdx.x;
    if (i >= total) return;
    size_t m = i / (size_t)K;
    int k = (int)(i - m * K);
    float f = src[i];
    __nv_bfloat16 hi = __float2bfloat16(f);
    __nv_bfloat16 lo = __float2bfloat16(f - __bfloat162float(hi));
    size_t base = m * (size_t)(3 * K);
    dst[base + k]         = hi;
    dst[base + K + k]     = lo;
    dst[base + 2 * K + k] = hi;
}

// ===================== cp.async helpers =====================
__device__ __forceinline__ void cp_async16(uint32_t dst, const void* src, bool pred) {
    int sz = pred ? 16 : 0;
    asm volatile("cp.async.cg.shared.global [%0], [%1], 16, %2;"
                 :: "r"(dst), "l"(src), "r"(sz) : "memory");
}
#define CP_COMMIT() asm volatile("cp.async.commit_group;" ::: "memory")
#define CP_WAIT(n)  asm volatile("cp.async.wait_group %0;" :: "n"(n) : "memory")

// ===================== tensor-core NT GEMM (WMMA / HMMA) =====================
// C[M,N] (op)= A3[M,Keff] * B3[N,Keff]^T   (bf16 in, fp32 accumulate)
enum { EP_NONE = 0, EP_ADD = 1, EP_TANH = 2 };

#define BM 128
#define BN 128
#define BK 32
#define LDS_PAD 40                      // bf16 elems per row (80B pitch)
#define STAGE_E (256 * LDS_PAD)         // (BM rows A + BN rows B) * 40
#define STAGE_B (STAGE_E * 2)           // bytes per stage = 20480
#define NSTAGE 3
#define SMEM_BYTES (NSTAGE * STAGE_B)   // 61440

__device__ __forceinline__ void load_stage(uint32_t sbase,
                                           const __nv_bfloat16* __restrict__ A,
                                           const __nv_bfloat16* __restrict__ Bm,
                                           int m0, int n0, int N, int Keff,
                                           int k0, int tid) {
#pragma unroll
    for (int l = 0; l < 2; l++) {
        int id = l * 256 + tid;
        int r = id >> 2, c = id & 3;
        uint32_t dst = sbase + (uint32_t)(r * LDS_PAD + c * 8) * 2;
        cp_async16(dst, A + (size_t)(m0 + r) * Keff + k0 + c * 8, true);
    }
#pragma unroll
    for (int l = 0; l < 2; l++) {
        int id = l * 256 + tid;
        int r = id >> 2, c = id & 3;
        uint32_t dst = sbase + (uint32_t)(BM * LDS_PAD + r * LDS_PAD + c * 8) * 2;
        bool ok = (n0 + r) < N;
        int gn = ok ? (n0 + r) : 0;
        cp_async16(dst, Bm + (size_t)gn * Keff + k0 + c * 8, ok);
    }
}

template <int EPI>
__global__ __launch_bounds__(256)
void gemm_wmma(const __nv_bfloat16* __restrict__ A,
               const __nv_bfloat16* __restrict__ Bm,
               float* __restrict__ C,
               int M, int N, int Keff) {
    extern __shared__ __nv_bfloat16 smem[];
    const uint32_t sm0 = (uint32_t)__cvta_generic_to_shared(smem);
    const int tid  = threadIdx.x;
    const int warp = tid >> 5, lane = tid & 31;
    const int wm = warp & 3;           // 4 warps over M: 32 rows each
    const int wn = warp >> 2;          // 2 warps over N: 64 cols each
    const int m0 = blockIdx.y * BM;
    const int n0 = blockIdx.x * BN;

    wmma::fragment<wmma::accumulator, 16, 16, 16, float> acc[2][4];
#pragma unroll
    for (int i = 0; i < 2; i++)
#pragma unroll
        for (int j = 0; j < 4; j++) wmma::fill_fragment(acc[i][j], 0.f);

    const int NK = Keff / BK;

    // prologue: stages 0..NSTAGE-2
#pragma unroll
    for (int s = 0; s < NSTAGE - 1; s++) {
        if (s < NK) {
            load_stage(sm0 + s * STAGE_B, A, Bm, m0, n0, N, Keff, s * BK, tid);
            CP_COMMIT();
        }
    }

    for (int kt = 0; kt < NK; kt++) {
        if (kt + NSTAGE - 1 < NK) {
            load_stage(sm0 + ((kt + NSTAGE - 1) % NSTAGE) * STAGE_B, A, Bm,
                       m0, n0, N, Keff, (kt + NSTAGE - 1) * BK, tid);
            CP_COMMIT();
        }
        if      (kt + 2 < NK) CP_WAIT(2);
        else if (kt + 1 < NK) CP_WAIT(1);
        else                  CP_WAIT(0);
        __syncthreads();

        const __nv_bfloat16* sA = smem + (size_t)(kt % NSTAGE) * STAGE_E;
        const __nv_bfloat16* sB = sA + BM * LDS_PAD;
#pragma unroll
        for (int ks = 0; ks < 2; ks++) {
            wmma::fragment<wmma::matrix_a, 16, 16, 16, __nv_bfloat16, wmma::row_major> af[2];
            wmma::fragment<wmma::matrix_b, 16, 16, 16, __nv_bfloat16, wmma::col_major> bfr[4];
#pragma unroll
            for (int i = 0; i < 2; i++)
                wmma::load_matrix_sync(af[i], sA + (wm * 32 + i * 16) * LDS_PAD + ks * 16, LDS_PAD);
#pragma unroll
            for (int j = 0; j < 4; j++)
                wmma::load_matrix_sync(bfr[j], sB + (wn * 64 + j * 16) * LDS_PAD + ks * 16, LDS_PAD);
#pragma unroll
            for (int i = 0; i < 2; i++)
#pragma unroll
                for (int j = 0; j < 4; j++)
                    wmma::mma_sync(acc[i][j], af[i], bfr[j], acc[i][j]);
        }
        __syncthreads();
    }

    // ---- epilogue: per-warp smem bounce, fused op ----
    float* scr = reinterpret_cast<float*>(smem) + warp * 256;
#pragma unroll
    for (int i = 0; i < 2; i++) {
#pragma unroll
        for (int j = 0; j < 4; j++) {
            wmma::store_matrix_sync(scr, acc[i][j], 16, wmma::mem_row_major);
            __syncwarp();
            int r0 = m0 + wm * 32 + i * 16;
            int c0 = n0 + wn * 64 + j * 16;
#pragma unroll
            for (int e = lane; e < 256; e += 32) {
                int rr = e >> 4, cc = e & 15;
                int gc = c0 + cc;
                if (gc < N) {
                    size_t off = (size_t)(r0 + rr) * N + gc;
                    float v = scr[e];
                    if (EPI == EP_ADD)  v += C[off];
                    if (EPI == EP_TANH) v = 30.f * tanhf(v * (1.f / 30.f));
                    C[off] = v;
                }
            }
            __syncwarp();
        }
    }
}

// ===================== elementwise / attention kernels =====================
__global__ void embed_kernel(const int* __restrict__ idx, const float* __restrict__ tok) {
    int i = blockIdx.x * 256 + threadIdx.x;
    int bt = i >> 10;
    int e  = i & (E_ - 1);
    float v = tok[(size_t)idx[bt] * E_ + e];
    g_x[i]  = v;
    g_x0[i] = v;
}

__global__ void rmsnorm_kernel(const float* __restrict__ x, const float* __restrict__ w,
                               float* __restrict__ out) {
    __shared__ float red[256];
    int row = blockIdx.x;
    const float* xr = x + (size_t)row * E_;
    float s = 0.f;
    for (int e = threadIdx.x; e < E_; e += 256) { float v = xr[e]; s += v * v; }
    red[threadIdx.x] = s;
    __syncthreads();
    for (int o = 128; o > 0; o >>= 1) {
        if (threadIdx.x < o) red[threadIdx.x] += red[threadIdx.x + o];
        __syncthreads();
    }
    float norm = rsqrtf(red[0] * (1.f / E_) + 1e-6f);
    for (int e = threadIdx.x; e < E_; e += 256)
        out[(size_t)row * E_ + e] = xr[e] * norm * w[e];
}

__global__ void gate_kernel(const float* __restrict__ hn, const float* __restrict__ vgw) {
    int i = blockIdx.x * 256 + threadIdx.x;
    if (i >= M_ * H_) return;
    int bt = i / H_, h = i % H_;
    const float* hr = hn + (size_t)bt * E_;
    const float* wr = vgw + h * 32;
    float s = 0.f;
#pragma unroll
    for (int c = 0; c < 32; c++) s = fmaf(hr[c], wr[c], s);
    g_gate[i] = 2.f / (1.f + expf(-s));
}

__global__ void rope_split_kernel(const float* __restrict__ qkv, int has_gate) {
    int bt = blockIdx.x;
    int b = bt / T_, t = bt % T_;
    const float* src = qkv + (size_t)bt * 3 * E_;
    float tf = (float)t;
#pragma unroll
    for (int which = 0; which < 2; ++which) {
        const float* sp = src + which * E_;
        float* dst = (which == 0) ? g_q : g_k;
        for (int item = threadIdx.x; item < H_ * 32; item += blockDim.x) {
            int h = item >> 5, p = item & 31;
            int d0 = 2 * p, d1 = 2 * p + 1;
            float ang0 = tf * powf(10000.f, -(float)(d0 & 31) * (1.f / 32.f));
            float ang1 = tf * powf(10000.f, -(float)(d1 & 31) * (1.f / 32.f));
            float s0, c0, s1, c1;
            sincosf(ang0, &s0, &c0);
            sincosf(ang1, &s1, &c1);
            float x0v = sp[h * HD_ + d0];
            float x1v = sp[h * HD_ + d1];
            float o0 = x0v * c0 - x1v * s0;
            float o1 = x1v * c1 + x0v * s1;
            size_t base = ((size_t)(b * H_ + h) * T_ + t) * HD_;
            dst[base + d0] = o0;
            dst[base + d1] = o1;
        }
    }
    for (int item = threadIdx.x; item < E_; item += blockDim.x) {
        int h = item >> 6, d = item & 63;
        float vv = src[2 * E_ + item];
        if (has_gate)
            vv += g_gate[bt * H_ + h] * g_x0[(size_t)bt * E_ + item];
        g_v[((size_t)(b * H_ + h) * T_ + t) * HD_ + d] = vv;
    }
}

__global__ __launch_bounds__(128) void attn_kernel() {
    __shared__ float Ks[64][64];
    __shared__ float Vs[64][64];
    int bh = blockIdx.y;
    int qi = blockIdx.x * 128 + threadIdx.x;
    const float* qp = g_q + ((size_t)bh * T_ + qi) * HD_;

    float q[64], o[64];
#pragma unroll
    for (int d4 = 0; d4 < 16; d4++) {
        float4 v = ((const float4*)qp)[d4];
        q[4*d4] = v.x; q[4*d4+1] = v.y; q[4*d4+2] = v.z; q[4*d4+3] = v.w;
    }
#pragma unroll
    for (int d = 0; d < 64; d++) o[d] = 0.f;
    float m = -1e30f, l = 0.f;

    int ntiles = blockIdx.x * 2 + 2;
    for (int kt = 0; kt < ntiles; kt++) {
        const float* kp = g_k + ((size_t)bh * T_ + kt * 64) * HD_;
        const float* vp = g_v + ((size_t)bh * T_ + kt * 64) * HD_;
        __syncthreads();
        for (int f = threadIdx.x; f < 64 * 16; f += 128) {
            int r = f >> 4, c4 = f & 15;
            ((float4*)&Ks[r][0])[c4] = ((const float4*)(kp + r * 64))[c4];
            ((float4*)&Vs[r][0])[c4] = ((const float4*)(vp + r * 64))[c4];
        }
        __syncthreads();
        int jmax = qi - kt * 64 + 1;
        if (jmax > 64) jmax = 64;
        for (int j = 0; j < jmax; j++) {
            float s = 0.f;
            const float4* kr = (const float4*)&Ks[j][0];
#pragma unroll
            for (int d4 = 0; d4 < 16; d4++) {
                float4 kk = kr[d4];
                s = fmaf(q[4*d4],   kk.x, s);
                s = fmaf(q[4*d4+1], kk.y, s);
                s = fmaf(q[4*d4+2], kk.z, s);
                s = fmaf(q[4*d4+3], kk.w, s);
            }
            s *= 0.125f;
            float mn   = fmaxf(m, s);
            float corr = __expf(m - mn);
            float p    = __expf(s - mn);
            l = l * corr + p;
            m = mn;
            const float4* vr = (const float4*)&Vs[j][0];
#pragma unroll
            for (int d4 = 0; d4 < 16; d4++) {
                float4 vv = vr[d4];
                o[4*d4]   = fmaf(p, vv.x, o[4*d4]   * corr);
                o[4*d4+1] = fmaf(p, vv.y, o[4*d4+1] * corr);
                o[4*d4+2] = fmaf(p, vv.z, o[4*d4+2] * corr);
                o[4*d4+3] = fmaf(p, vv.w, o[4*d4+3] * corr);
            }
        }
    }
    float inv = 1.f / l;
    int b = bh / H_, h = bh % H_;
    float* op = g_o + ((size_t)(b * T_ + qi)) * E_ + h * HD_;
#pragma unroll
    for (int d4 = 0; d4 < 16; d4++) {
        float4 vv = make_float4(o[4*d4] * inv, o[4*d4+1] * inv,
                                o[4*d4+2] * inv, o[4*d4+3] * inv);
        ((float4*)op)[d4] = vv;
    }
}

__global__ void swiglu_kernel() {
    size_t i = (size_t)blockIdx.x * 256 + threadIdx.x;
    float gv = g_g[i];
    float s = gv / (1.f + expf(-gv));
    g_g[i] = s * g_u[i];
}

// ===================== host-side GEMM launcher =====================
template <int EPI>
static void run_gemm(const __nv_bfloat16* A3, const __nv_bfloat16* B3, float* C,
                     int M, int N, int Keff) {
    dim3 grid((N + BN - 1) / BN, M / BM);
    gemm_wmma<EPI><<<grid, 256, SMEM_BYTES>>>(A3, B3, C, M, N, Keff);
}

// ===================== launch =====================
extern "C" void kernel_launch(void* const* d_in, const int* in_sizes, int n_in,
                              void* d_out, int out_size) {
    const int*   idx  = (const int*)  d_in[0];
    const float* tok  = (const float*)d_in[1];
    const float* ln1  = (const float*)d_in[2];
    const float* qkvw = (const float*)d_in[3];
    const float* outw = (const float*)d_in[4];
    const float* vgw  = (const float*)d_in[5];
    const float* ln2  = (const float*)d_in[6];
    const float* wgw  = (const float*)d_in[7];
    const float* wuw  = (const float*)d_in[8];
    const float* wdw  = (const float*)d_in[9];
    const float* lnf  = (const float*)d_in[10];
    float* out = (float*)d_out;

    cudaFuncSetAttribute(gemm_wmma<EP_NONE>, cudaFuncAttributeMaxDynamicSharedMemorySize, SMEM_BYTES);
    cudaFuncSetAttribute(gemm_wmma<EP_ADD>,  cudaFuncAttributeMaxDynamicSharedMemorySize, SMEM_BYTES);
    cudaFuncSetAttribute(gemm_wmma<EP_TANH>, cudaFuncAttributeMaxDynamicSharedMemorySize, SMEM_BYTES);

    float *x, *h, *qkv, *ob, *gb, *ub;
    cudaGetSymbolAddress((void**)&x,   g_x);
    cudaGetSymbolAddress((void**)&h,   g_h);
    cudaGetSymbolAddress((void**)&qkv, g_qkv);
    cudaGetSymbolAddress((void**)&ob,  g_o);
    cudaGetSymbolAddress((void**)&gb,  g_g);
    cudaGetSymbolAddress((void**)&ub,  g_u);

    __nv_bfloat16 *qkvw3, *outw3, *wg3, *wu3, *wd3, *tok3, *a3s, *a3b;
    cudaGetSymbolAddress((void**)&qkvw3, g_qkvw3);
    cudaGetSymbolAddress((void**)&outw3, g_outw3);
    cudaGetSymbolAddress((void**)&wg3,   g_wg3);
    cudaGetSymbolAddress((void**)&wu3,   g_wu3);
    cudaGetSymbolAddress((void**)&wd3,   g_wd3);
    cudaGetSymbolAddress((void**)&tok3,  g_tok3);
    cudaGetSymbolAddress((void**)&a3s,   g_a3s);
    cudaGetSymbolAddress((void**)&a3b,   g_a3b);

    // ---- weight split conversion (all B-role) ----
    {
        size_t n;
        n = (size_t)L_ * 3 * E_ * E_;
        cvt_b3<<<(unsigned)((n + 255) / 256), 256>>>(qkvw, qkvw3, E_, n);
        n = (size_t)L_ * E_ * E_;
        cvt_b3<<<(unsigned)((n + 255) / 256), 256>>>(outw, outw3, E_, n);
        n = (size_t)L_ * FF_ * E_;
        cvt_b3<<<(unsigned)((n + 255) / 256), 256>>>(wgw, wg3, E_, n);
        cvt_b3<<<(unsigned)((n + 255) / 256), 256>>>(wuw, wu3, E_, n);
        n = (size_t)L_ * E_ * FF_;
        cvt_b3<<<(unsigned)((n + 255) / 256), 256>>>(wdw, wd3, FF_, n);
        n = (size_t)V_ * E_;
        cvt_b3<<<(unsigned)((n + 255) / 256), 256>>>(tok, tok3, E_, n);
    }

    embed_kernel<<<(M_ * E_) / 256, 256>>>(idx, tok);

    const int K3E = 3 * E_;    // 3072
    const int K3F = 3 * FF_;   // 12288

    for (int i = 0; i < L_; i++) {
        rmsnorm_kernel<<<M_, 256>>>(x, ln1 + i * E_, h);
        cvt_a3<<<(M_ * E_) / 256, 256>>>(h, a3s, E_);
        run_gemm<EP_NONE>(a3s, qkvw3 + (size_t)i * 3 * E_ * K3E, qkv, M_, 3 * E_, K3E);
        if (i & 1)
            gate_kernel<<<(M_ * H_ + 255) / 256, 256>>>(h, vgw + (size_t)i * H_ * 32);
        rope_split_kernel<<<M_, 256>>>(qkv, i & 1);
        attn_kernel<<<dim3(T_ / 128, B_ * H_), 128>>>();

        cvt_a3<<<(M_ * E_) / 256, 256>>>(ob, a3s, E_);
        run_gemm<EP_ADD>(a3s, outw3 + (size_t)i * E_ * K3E, x, M_, E_, K3E);

        rmsnorm_kernel<<<M_, 256>>>(x, ln2 + i * E_, h);
        cvt_a3<<<(M_ * E_) / 256, 256>>>(h, a3s, E_);
        run_gemm<EP_NONE>(a3s, wg3 + (size_t)i * FF_ * K3E, gb, M_, FF_, K3E);
        run_gemm<EP_NONE>(a3s, wu3 + (size_t)i * FF_ * K3E, ub, M_, FF_, K3E);
        swiglu_kernel<<<(M_ * FF_) / 256, 256>>>();
        cvt_a3<<<(M_ * FF_) / 256, 256>>>(gb, a3b, FF_);
        run_gemm<EP_ADD>(a3b, wd3 + (size_t)i * E_ * K3F, x, M_, E_, K3F);
    }

    rmsnorm_kernel<<<M_, 256>>>(x, lnf, h);
    cvt_a3<<<(M_ * E_) / 256, 256>>>(h, a3s, E_);
    run_gemm<EP_TANH>(a3s, tok3, out, M_, V_, K3E);
}

// round 4
// speedup vs baseline: 1.7944x; 1.0762x over previous
#include <cuda_runtime.h>
#include <cuda_bf16.h>
#include <mma.h>
#include <math.h>
#include <stdint.h>

using namespace nvcuda;

#define B_  2
#define T_  1024
#define E_  1024
#define H_  16
#define HD_ 64
#define FF_ 4096
#define L_  8
#define V_  50257
#define M_  (B_*T_)   // 2048

// ===================== scratch (device globals) =====================
__device__ float g_x   [M_*E_];
__device__ float g_x0  [M_*E_];
__device__ float g_h   [M_*E_];
__device__ float g_qkv [M_*3*E_];
__device__ float g_q   [M_*E_];
__device__ float g_k   [M_*E_];
__device__ float g_v   [M_*E_];
__device__ float g_gate[M_*H_];
__device__ float g_gu  [(size_t)M_*2*FF_];          // [wg | wu] outputs

// bf16 [hi|lo] 2K-layout buffers
__device__ __nv_bfloat16 g_wqkv2[(size_t)L_*3*E_*2*E_];
__device__ __nv_bfloat16 g_wout2[(size_t)L_*E_*2*E_];
__device__ __nv_bfloat16 g_wgu2 [(size_t)L_*2*FF_*2*E_];   // rows: [wg(FF)|wu(FF)] per layer
__device__ __nv_bfloat16 g_wd2  [(size_t)L_*E_*2*FF_];
__device__ __nv_bfloat16 g_tok2 [(size_t)V_*2*E_];
__device__ __nv_bfloat16 g_a2s  [(size_t)M_*2*E_];
__device__ __nv_bfloat16 g_a2b  [(size_t)M_*2*FF_];

// ===================== vectorized hi/lo split conversion =====================
// src row-major [rows, K] fp32 -> dst [rows', 2K] bf16 with dst row =
// (r / RPL) * ostride + ooff + (r % RPL). 8 elements per thread.
__global__ void cvt2(const float* __restrict__ src, __nv_bfloat16* __restrict__ dst,
                     int K, long long total8, int RPL, long long ostride, int ooff) {
    long long i8 = (long long)blockIdx.x * 256 + threadIdx.x;
    if (i8 >= total8) return;
    long long i = i8 * 8;
    long long r = i / K;
    int k = (int)(i - r * (long long)K);
    long long layer = r / RPL;
    long long dr = layer * ostride + ooff + (r - layer * RPL);

    const float4* sp = (const float4*)(src + r * (long long)K + k);
    float4 f0 = sp[0], f1 = sp[1];
    float fv[8] = {f0.x, f0.y, f0.z, f0.w, f1.x, f1.y, f1.z, f1.w};

    union { __nv_bfloat162 b2[4]; uint4 u; } hi, lo;
#pragma unroll
    for (int j = 0; j < 4; j++) {
        __nv_bfloat16 h0 = __float2bfloat16(fv[2*j]);
        __nv_bfloat16 h1 = __float2bfloat16(fv[2*j+1]);
        float l0 = fv[2*j]   - __bfloat162float(h0);
        float l1 = fv[2*j+1] - __bfloat162float(h1);
        hi.b2[j] = __nv_bfloat162(h0, h1);
        lo.b2[j] = __floats2bfloat162_rn(l0, l1);
    }
    __nv_bfloat16* dbase = dst + dr * (long long)(2 * K);
    *((uint4*)(dbase + k))     = hi.u;
    *((uint4*)(dbase + K + k)) = lo.u;
}

// ===================== cp.async helpers =====================
__device__ __forceinline__ void cp_async16(uint32_t dst, const void* src, bool pred) {
    int sz = pred ? 16 : 0;
    asm volatile("cp.async.cg.shared.global [%0], [%1], 16, %2;"
                 :: "r"(dst), "l"(src), "r"(sz) : "memory");
}
#define CP_COMMIT() asm volatile("cp.async.commit_group;" ::: "memory")
#define CP_WAIT(n)  asm volatile("cp.async.wait_group %0;" :: "n"(n) : "memory")

// ===================== tensor-core NT GEMM (WMMA, 3-term split via remap) ===
// Effective C[M,N] (op)= A3[M,3K] * B3[N,3K]^T with
//   A3 = [Ah|Ah|Al] mapped from A2=[Ah|Al],  B3 = [Bh|Bl|Bh] from B2=[Bh|Bl]
enum { EP_NONE = 0, EP_ADD = 1, EP_TANH = 2 };

#define BM 128
#define BN 128
#define BK 32
#define LDS_PAD 40
#define STAGE_E (256 * LDS_PAD)
#define STAGE_B (STAGE_E * 2)          // 20480 bytes
#define NSTAGE 3
#define SMEM_BYTES (NSTAGE * STAGE_B)  // 61440

__device__ __forceinline__ void load_stage(uint32_t sbase,
                                           const __nv_bfloat16* __restrict__ A,
                                           const __nv_bfloat16* __restrict__ Bm,
                                           int m0, int n0, int N, int K,
                                           int kc, int tid) {
    const int kA  = (kc < K)     ? kc : kc - K;
    const int kB  = (kc < 2 * K) ? kc : kc - 2 * K;
    const int ld2 = 2 * K;
#pragma unroll
    for (int l = 0; l < 2; l++) {
        int id = l * 256 + tid;
        int r = id >> 2, c = id & 3;
        uint32_t dst = sbase + (uint32_t)(r * LDS_PAD + c * 8) * 2;
        cp_async16(dst, A + (size_t)(m0 + r) * ld2 + kA + c * 8, true);
    }
#pragma unroll
    for (int l = 0; l < 2; l++) {
        int id = l * 256 + tid;
        int r = id >> 2, c = id & 3;
        uint32_t dst = sbase + (uint32_t)(BM * LDS_PAD + r * LDS_PAD + c * 8) * 2;
        bool ok = (n0 + r) < N;
        int gn = ok ? (n0 + r) : 0;
        cp_async16(dst, Bm + (size_t)gn * ld2 + kB + c * 8, ok);
    }
}

template <int EPI>
__global__ __launch_bounds__(256, 2)
void gemm_wmma(const __nv_bfloat16* __restrict__ A,
               const __nv_bfloat16* __restrict__ Bm,
               float* __restrict__ C,
               int M, int N, int K) {
    extern __shared__ __nv_bfloat16 smem[];
    const uint32_t sm0 = (uint32_t)__cvta_generic_to_shared(smem);
    const int tid  = threadIdx.x;
    const int warp = tid >> 5, lane = tid & 31;
    const int wm = warp & 3;
    const int wn = warp >> 2;
    const int m0 = blockIdx.y * BM;
    const int n0 = blockIdx.x * BN;
    const int NK = (3 * K) / BK;

    wmma::fragment<wmma::accumulator, 16, 16, 16, float> acc[2][4];
#pragma unroll
    for (int i = 0; i < 2; i++)
#pragma unroll
        for (int j = 0; j < 4; j++) wmma::fill_fragment(acc[i][j], 0.f);

    // prologue: stages 0,1
#pragma unroll
    for (int s = 0; s < NSTAGE - 1; s++) {
        load_stage(sm0 + s * STAGE_B, A, Bm, m0, n0, N, K, s * BK, tid);
        CP_COMMIT();
    }

    for (int kt = 0; kt < NK; kt++) {
        CP_WAIT(1);
        __syncthreads();
        int cn = kt + NSTAGE - 1;
        if (cn < NK)
            load_stage(sm0 + (cn % NSTAGE) * STAGE_B, A, Bm, m0, n0, N, K,
                       cn * BK, tid);
        CP_COMMIT();

        const __nv_bfloat16* sA = smem + (size_t)(kt % NSTAGE) * STAGE_E;
        const __nv_bfloat16* sB = sA + BM * LDS_PAD;
#pragma unroll
        for (int ks = 0; ks < 2; ks++) {
            wmma::fragment<wmma::matrix_a, 16, 16, 16, __nv_bfloat16, wmma::row_major> af[2];
            wmma::fragment<wmma::matrix_b, 16, 16, 16, __nv_bfloat16, wmma::col_major> bfr[4];
#pragma unroll
            for (int i = 0; i < 2; i++)
                wmma::load_matrix_sync(af[i], sA + (wm * 32 + i * 16) * LDS_PAD + ks * 16, LDS_PAD);
#pragma unroll
            for (int j = 0; j < 4; j++)
                wmma::load_matrix_sync(bfr[j], sB + (wn * 64 + j * 16) * LDS_PAD + ks * 16, LDS_PAD);
#pragma unroll
            for (int i = 0; i < 2; i++)
#pragma unroll
                for (int j = 0; j < 4; j++)
                    wmma::mma_sync(acc[i][j], af[i], bfr[j], acc[i][j]);
        }
    }
    __syncthreads();

    // epilogue: per-warp smem bounce, fused op
    float* scr = reinterpret_cast<float*>(smem) + warp * 256;
#pragma unroll
    for (int i = 0; i < 2; i++) {
#pragma unroll
        for (int j = 0; j < 4; j++) {
            wmma::store_matrix_sync(scr, acc[i][j], 16, wmma::mem_row_major);
            __syncwarp();
            int r0 = m0 + wm * 32 + i * 16;
            int c0 = n0 + wn * 64 + j * 16;
#pragma unroll
            for (int e = lane; e < 256; e += 32) {
                int rr = e >> 4, cc = e & 15;
                int gc = c0 + cc;
                if (gc < N) {
                    size_t off = (size_t)(r0 + rr) * N + gc;
                    float v = scr[e];
                    if (EPI == EP_ADD)  v += C[off];
                    if (EPI == EP_TANH) v = 30.f * tanhf(v * (1.f / 30.f));
                    C[off] = v;
                }
            }
            __syncwarp();
        }
    }
}

// ===================== elementwise / attention kernels =====================
__global__ void embed_kernel(const int* __restrict__ idx, const float* __restrict__ tok) {
    int i = blockIdx.x * 256 + threadIdx.x;
    int bt = i >> 10;
    int e  = i & (E_ - 1);
    float v = tok[(size_t)idx[bt] * E_ + e];
    g_x[i]  = v;
    g_x0[i] = v;
}

// rmsnorm + optional fp32 h + split bf16 activation ([hi|lo] 2E row)
__global__ void rmsnorm_split(const float* __restrict__ x, const float* __restrict__ w,
                              float* __restrict__ h, __nv_bfloat16* __restrict__ a2) {
    __shared__ float red[8];
    int row = blockIdx.x;
    int tid = threadIdx.x;
    const float4 xv = ((const float4*)(x + (size_t)row * E_))[tid];
    float s = xv.x*xv.x + xv.y*xv.y + xv.z*xv.z + xv.w*xv.w;
#pragma unroll
    for (int o = 16; o; o >>= 1) s += __shfl_xor_sync(0xFFFFFFFFu, s, o);
    if ((tid & 31) == 0) red[tid >> 5] = s;
    __syncthreads();
    if (tid == 0) {
        float t = 0.f;
#pragma unroll
        for (int i = 0; i < 8; i++) t += red[i];
        red[0] = rsqrtf(t * (1.f / E_) + 1e-6f);
    }
    __syncthreads();
    float norm = red[0];
    const float4 wv = ((const float4*)w)[tid];
    float v[4] = {xv.x*norm*wv.x, xv.y*norm*wv.y, xv.z*norm*wv.z, xv.w*norm*wv.w};
    if (h) ((float4*)(h + (size_t)row * E_))[tid] = make_float4(v[0], v[1], v[2], v[3]);
    union { __nv_bfloat162 b2[2]; uint2 u; } hi, lo;
#pragma unroll
    for (int j = 0; j < 2; j++) {
        __nv_bfloat16 h0 = __float2bfloat16(v[2*j]);
        __nv_bfloat16 h1 = __float2bfloat16(v[2*j+1]);
        hi.b2[j] = __nv_bfloat162(h0, h1);
        lo.b2[j] = __floats2bfloat162_rn(v[2*j] - __bfloat162float(h0),
                                         v[2*j+1] - __bfloat162float(h1));
    }
    __nv_bfloat16* dbase = a2 + (size_t)row * 2 * E_ + tid * 4;
    *((uint2*)dbase)        = hi.u;
    *((uint2*)(dbase + E_)) = lo.u;
}

__global__ void gate_kernel(const float* __restrict__ hn, const float* __restrict__ vgw) {
    int i = blockIdx.x * 256 + threadIdx.x;
    if (i >= M_ * H_) return;
    int bt = i / H_, h = i % H_;
    const float* hr = hn + (size_t)bt * E_;
    const float* wr = vgw + h * 32;
    float s = 0.f;
#pragma unroll
    for (int c = 0; c < 32; c++) s = fmaf(hr[c], wr[c], s);
    g_gate[i] = 2.f / (1.f + expf(-s));
}

__global__ void rope_split_kernel(const float* __restrict__ qkv, int has_gate) {
    int bt = blockIdx.x;
    int b = bt / T_, t = bt % T_;
    const float* src = qkv + (size_t)bt * 3 * E_;
    float tf = (float)t;
#pragma unroll
    for (int which = 0; which < 2; ++which) {
        const float* sp = src + which * E_;
        float* dst = (which == 0) ? g_q : g_k;
        for (int item = threadIdx.x; item < H_ * 32; item += blockDim.x) {
            int h = item >> 5, p = item & 31;
            int d0 = 2 * p, d1 = 2 * p + 1;
            float ang0 = tf * powf(10000.f, -(float)(d0 & 31) * (1.f / 32.f));
            float ang1 = tf * powf(10000.f, -(float)(d1 & 31) * (1.f / 32.f));
            float s0, c0, s1, c1;
            sincosf(ang0, &s0, &c0);
            sincosf(ang1, &s1, &c1);
            float x0v = sp[h * HD_ + d0];
            float x1v = sp[h * HD_ + d1];
            float o0 = x0v * c0 - x1v * s0;
            float o1 = x1v * c1 + x0v * s1;
            size_t base = ((size_t)(b * H_ + h) * T_ + t) * HD_;
            dst[base + d0] = o0;
            dst[base + d1] = o1;
        }
    }
    for (int item = threadIdx.x; item < E_; item += blockDim.x) {
        int h = item >> 6, d = item & 63;
        float vv = src[2 * E_ + item];
        if (has_gate)
            vv += g_gate[bt * H_ + h] * g_x0[(size_t)bt * E_ + item];
        g_v[((size_t)(b * H_ + h) * T_ + t) * HD_ + d] = vv;
    }
}

// flash attention fp32; writes split bf16 [hi|lo] directly into g_a2s
__global__ __launch_bounds__(128) void attn_kernel() {
    __shared__ float Ks[64][64];
    __shared__ float Vs[64][64];
    int bh = blockIdx.y;
    int qi = blockIdx.x * 128 + threadIdx.x;
    const float* qp = g_q + ((size_t)bh * T_ + qi) * HD_;

    float q[64], o[64];
#pragma unroll
    for (int d4 = 0; d4 < 16; d4++) {
        float4 v = ((const float4*)qp)[d4];
        q[4*d4] = v.x; q[4*d4+1] = v.y; q[4*d4+2] = v.z; q[4*d4+3] = v.w;
    }
#pragma unroll
    for (int d = 0; d < 64; d++) o[d] = 0.f;
    float m = -1e30f, l = 0.f;

    int ntiles = blockIdx.x * 2 + 2;
    for (int kt = 0; kt < ntiles; kt++) {
        const float* kp = g_k + ((size_t)bh * T_ + kt * 64) * HD_;
        const float* vp = g_v + ((size_t)bh * T_ + kt * 64) * HD_;
        __syncthreads();
        for (int f = threadIdx.x; f < 64 * 16; f += 128) {
            int r = f >> 4, c4 = f & 15;
            ((float4*)&Ks[r][0])[c4] = ((const float4*)(kp + r * 64))[c4];
            ((float4*)&Vs[r][0])[c4] = ((const float4*)(vp + r * 64))[c4];
        }
        __syncthreads();
        int jmax = qi - kt * 64 + 1;
        if (jmax > 64) jmax = 64;
        for (int j = 0; j < jmax; j++) {
            float s = 0.f;
            const float4* kr = (const float4*)&Ks[j][0];
#pragma unroll
            for (int d4 = 0; d4 < 16; d4++) {
                float4 kk = kr[d4];
                s = fmaf(q[4*d4],   kk.x, s);
                s = fmaf(q[4*d4+1], kk.y, s);
                s = fmaf(q[4*d4+2], kk.z, s);
                s = fmaf(q[4*d4+3], kk.w, s);
            }
            s *= 0.125f;
            float mn   = fmaxf(m, s);
            float corr = __expf(m - mn);
            float p    = __expf(s - mn);
            l = l * corr + p;
            m = mn;
            const float4* vr = (const float4*)&Vs[j][0];
#pragma unroll
            for (int d4 = 0; d4 < 16; d4++) {
                float4 vv = vr[d4];
                o[4*d4]   = fmaf(p, vv.x, o[4*d4]   * corr);
                o[4*d4+1] = fmaf(p, vv.y, o[4*d4+1] * corr);
                o[4*d4+2] = fmaf(p, vv.z, o[4*d4+2] * corr);
                o[4*d4+3] = fmaf(p, vv.w, o[4*d4+3] * corr);
            }
        }
    }
    float inv = 1.f / l;
    int b = bh / H_, h = bh % H_;
    __nv_bfloat16* hb = g_a2s + (size_t)(b * T_ + qi) * 2 * E_ + h * HD_;
#pragma unroll
    for (int d4 = 0; d4 < 16; d4++) {
        float v0 = o[4*d4]   * inv, v1 = o[4*d4+1] * inv;
        float v2 = o[4*d4+2] * inv, v3 = o[4*d4+3] * inv;
        __nv_bfloat16 h0 = __float2bfloat16(v0), h1 = __float2bfloat16(v1);
        __nv_bfloat16 h2 = __float2bfloat16(v2), h3 = __float2bfloat16(v3);
        union { __nv_bfloat162 b2[2]; uint2 u; } hi, lo;
        hi.b2[0] = __nv_bfloat162(h0, h1);
        hi.b2[1] = __nv_bfloat162(h2, h3);
        lo.b2[0] = __floats2bfloat162_rn(v0 - __bfloat162float(h0), v1 - __bfloat162float(h1));
        lo.b2[1] = __floats2bfloat162_rn(v2 - __bfloat162float(h2), v3 - __bfloat162float(h3));
        *((uint2*)(hb + d4 * 4))       = hi.u;
        *((uint2*)(hb + E_ + d4 * 4))  = lo.u;
    }
}

// swiglu: read [g|u] from g_gu, write split bf16 activation into g_a2b
__global__ void swiglu_split() {
    size_t i4 = (size_t)blockIdx.x * 256 + threadIdx.x;   // < M_*FF_/4
    size_t m = i4 / (FF_ / 4);
    int f4 = (int)(i4 - m * (FF_ / 4));
    const float* row = g_gu + m * (size_t)(2 * FF_);
    float4 g = ((const float4*)row)[f4];
    float4 u = ((const float4*)(row + FF_))[f4];
    float v[4];
    v[0] = (g.x / (1.f + expf(-g.x))) * u.x;
    v[1] = (g.y / (1.f + expf(-g.y))) * u.y;
    v[2] = (g.z / (1.f + expf(-g.z))) * u.z;
    v[3] = (g.w / (1.f + expf(-g.w))) * u.w;
    union { __nv_bfloat162 b2[2]; uint2 uu; } hi, lo;
#pragma unroll
    for (int j = 0; j < 2; j++) {
        __nv_bfloat16 h0 = __float2bfloat16(v[2*j]);
        __nv_bfloat16 h1 = __float2bfloat16(v[2*j+1]);
        hi.b2[j] = __nv_bfloat162(h0, h1);
        lo.b2[j] = __floats2bfloat162_rn(v[2*j] - __bfloat162float(h0),
                                         v[2*j+1] - __bfloat162float(h1));
    }
    __nv_bfloat16* dbase = g_a2b + m * (size_t)(2 * FF_) + f4 * 4;
    *((uint2*)dbase)         = hi.uu;
    *((uint2*)(dbase + FF_)) = lo.uu;
}

// ===================== host-side launchers =====================
template <int EPI>
static void run_gemm(const __nv_bfloat16* A2, const __nv_bfloat16* B2, float* C,
                     int M, int N, int K) {
    dim3 grid((N + BN - 1) / BN, M / BM);
    gemm_wmma<EPI><<<grid, 256, SMEM_BYTES>>>(A2, B2, C, M, N, K);
}

static void run_cvt2(const float* src, __nv_bfloat16* dst, int K, long long rows,
                     int RPL, long long ostride, int ooff) {
    long long total8 = rows * K / 8;
    unsigned blocks = (unsigned)((total8 + 255) / 256);
    cvt2<<<blocks, 256>>>(src, dst, K, total8, RPL, ostride, ooff);
}

// ===================== launch =====================
extern "C" void kernel_launch(void* const* d_in, const int* in_sizes, int n_in,
                              void* d_out, int out_size) {
    const int*   idx  = (const int*)  d_in[0];
    const float* tok  = (const float*)d_in[1];
    const float* ln1  = (const float*)d_in[2];
    const float* qkvw = (const float*)d_in[3];
    const float* outw = (const float*)d_in[4];
    const float* vgw  = (const float*)d_in[5];
    const float* ln2  = (const float*)d_in[6];
    const float* wgw  = (const float*)d_in[7];
    const float* wuw  = (const float*)d_in[8];
    const float* wdw  = (const float*)d_in[9];
    const float* lnf  = (const float*)d_in[10];
    float* out = (float*)d_out;

    cudaFuncSetAttribute(gemm_wmma<EP_NONE>, cudaFuncAttributeMaxDynamicSharedMemorySize, SMEM_BYTES);
    cudaFuncSetAttribute(gemm_wmma<EP_ADD>,  cudaFuncAttributeMaxDynamicSharedMemorySize, SMEM_BYTES);
    cudaFuncSetAttribute(gemm_wmma<EP_TANH>, cudaFuncAttributeMaxDynamicSharedMemorySize, SMEM_BYTES);

    float *x, *h, *qkv, *gu;
    cudaGetSymbolAddress((void**)&x,   g_x);
    cudaGetSymbolAddress((void**)&h,   g_h);
    cudaGetSymbolAddress((void**)&qkv, g_qkv);
    cudaGetSymbolAddress((void**)&gu,  g_gu);

    __nv_bfloat16 *wqkv2, *wout2, *wgu2, *wd2, *tok2, *a2s, *a2b;
    cudaGetSymbolAddress((void**)&wqkv2, g_wqkv2);
    cudaGetSymbolAddress((void**)&wout2, g_wout2);
    cudaGetSymbolAddress((void**)&wgu2,  g_wgu2);
    cudaGetSymbolAddress((void**)&wd2,   g_wd2);
    cudaGetSymbolAddress((void**)&tok2,  g_tok2);
    cudaGetSymbolAddress((void**)&a2s,   g_a2s);
    cudaGetSymbolAddress((void**)&a2b,   g_a2b);

    // ---- weight split conversions ([hi|lo], vectorized) ----
    run_cvt2(qkvw, wqkv2, E_,  (long long)L_ * 3 * E_, 3 * E_,     3 * E_,     0);
    run_cvt2(outw, wout2, E_,  (long long)L_ * E_,     E_,         E_,         0);
    run_cvt2(wgw,  wgu2,  E_,  (long long)L_ * FF_,    FF_,        2 * FF_,    0);
    run_cvt2(wuw,  wgu2,  E_,  (long long)L_ * FF_,    FF_,        2 * FF_,    FF_);
    run_cvt2(wdw,  wd2,   FF_, (long long)L_ * E_,     E_,         E_,         0);
    run_cvt2(tok,  tok2,  E_,  (long long)V_,          V_,         V_,         0);

    embed_kernel<<<(M_ * E_) / 256, 256>>>(idx, tok);

    for (int i = 0; i < L_; i++) {
        rmsnorm_split<<<M_, 256>>>(x, ln1 + i * E_, h, a2s);
        run_gemm<EP_NONE>(a2s, wqkv2 + (size_t)i * 3 * E_ * 2 * E_, qkv, M_, 3 * E_, E_);
        if (i & 1)
            gate_kernel<<<(M_ * H_ + 255) / 256, 256>>>(h, vgw + (size_t)i * H_ * 32);
        rope_split_kernel<<<M_, 256>>>(qkv, i & 1);
        attn_kernel<<<dim3(T_ / 128, B_ * H_), 128>>>();   // writes split into a2s
        run_gemm<EP_ADD>(a2s, wout2 + (size_t)i * E_ * 2 * E_, x, M_, E_, E_);

        rmsnorm_split<<<M_, 256>>>(x, ln2 + i * E_, nullptr, a2s);
        run_gemm<EP_NONE>(a2s, wgu2 + (size_t)i * 2 * FF_ * 2 * E_, gu, M_, 2 * FF_, E_);
        swiglu_split<<<(M_ * FF_ / 4) / 256, 256>>>();
        run_gemm<EP_ADD>(a2b, wd2 + (size_t)i * E_ * 2 * FF_, x, M_, E_, FF_);
    }

    rmsnorm_split<<<M_, 256>>>(x, lnf, nullptr, a2s);
    run_gemm<EP_TANH>(a2s, tok2, out, M_, V_, E_);
}

// round 5
// speedup vs baseline: 1.9767x; 1.1015x over previous
#include <cuda_runtime.h>
#include <cuda_bf16.h>
#include <mma.h>
#include <math.h>
#include <stdint.h>

using namespace nvcuda;

#define B_  2
#define T_  1024
#define E_  1024
#define H_  16
#define HD_ 64
#define FF_ 4096
#define L_  8
#define V_  50257
#define M_  (B_*T_)   // 2048

// ===================== scratch (device globals) =====================
__device__ float g_x   [M_*E_];
__device__ float g_x0  [M_*E_];
__device__ float g_h   [M_*E_];
__device__ float g_qkv [M_*3*E_];
__device__ float g_q   [M_*E_];
__device__ float g_k   [M_*E_];
__device__ float g_v   [M_*E_];
__device__ float g_gate[M_*H_];
__device__ float g_gu  [(size_t)M_*2*FF_];          // [wg | wu] outputs

// bf16 [hi|lo] 2K-layout buffers
__device__ __nv_bfloat16 g_wqkv2[(size_t)L_*3*E_*2*E_];
__device__ __nv_bfloat16 g_wout2[(size_t)L_*E_*2*E_];
__device__ __nv_bfloat16 g_wgu2 [(size_t)L_*2*FF_*2*E_];   // rows: [wg(FF)|wu(FF)]
__device__ __nv_bfloat16 g_wd2  [(size_t)L_*E_*2*FF_];
__device__ __nv_bfloat16 g_tok2 [(size_t)V_*2*E_];
__device__ __nv_bfloat16 g_a2s  [(size_t)M_*2*E_];
__device__ __nv_bfloat16 g_a2b  [(size_t)M_*2*FF_];

// ===================== vectorized hi/lo split conversion =====================
__global__ void cvt2(const float* __restrict__ src, __nv_bfloat16* __restrict__ dst,
                     int K, long long total8, int RPL, long long ostride, int ooff) {
    long long i8 = (long long)blockIdx.x * 256 + threadIdx.x;
    if (i8 >= total8) return;
    long long i = i8 * 8;
    long long r = i / K;
    int k = (int)(i - r * (long long)K);
    long long layer = r / RPL;
    long long dr = layer * ostride + ooff + (r - layer * RPL);

    const float4* sp = (const float4*)(src + r * (long long)K + k);
    float4 f0 = sp[0], f1 = sp[1];
    float fv[8] = {f0.x, f0.y, f0.z, f0.w, f1.x, f1.y, f1.z, f1.w};

    union { __nv_bfloat162 b2[4]; uint4 u; } hi, lo;
#pragma unroll
    for (int j = 0; j < 4; j++) {
        __nv_bfloat16 h0 = __float2bfloat16(fv[2*j]);
        __nv_bfloat16 h1 = __float2bfloat16(fv[2*j+1]);
        hi.b2[j] = __nv_bfloat162(h0, h1);
        lo.b2[j] = __floats2bfloat162_rn(fv[2*j]   - __bfloat162float(h0),
                                         fv[2*j+1] - __bfloat162float(h1));
    }
    __nv_bfloat16* dbase = dst + dr * (long long)(2 * K);
    *((uint4*)(dbase + k))     = hi.u;
    *((uint4*)(dbase + K + k)) = lo.u;
}

// ===================== cp.async helpers =====================
__device__ __forceinline__ void cp_async16(uint32_t dst, const void* src, bool pred) {
    int sz = pred ? 16 : 0;
    asm volatile("cp.async.cg.shared.global [%0], [%1], 16, %2;"
                 :: "r"(dst), "l"(src), "r"(sz) : "memory");
}
#define CP_COMMIT() asm volatile("cp.async.commit_group;" ::: "memory")
#define CP_WAIT(n)  asm volatile("cp.async.wait_group %0;" :: "n"(n) : "memory")

// ===================== tensor-core NT GEMM (WMMA, 3-term split via remap) ===
enum { EP_NONE = 0, EP_ADD = 1, EP_TANH = 2 };

#define BN 128
#define BK 64
#define LDS_PAD 72                     // 64 + 8 bf16; pitch 144B, bank-offset 4/row
#define NSTAGE 3

template <int BMv>
__device__ __forceinline__ void load_stage64(uint32_t sbase,
                                             const __nv_bfloat16* __restrict__ A,
                                             const __nv_bfloat16* __restrict__ Bm,
                                             int m0, int n0, int N, int K,
                                             int kc, int tid) {
    const int kA  = (kc < K)     ? kc : kc - K;       // A3 = [Ah|Ah|Al]
    const int kB  = (kc < 2 * K) ? kc : kc - 2 * K;   // B3 = [Bh|Bl|Bh]
    const int ld2 = 2 * K;
#pragma unroll
    for (int it = 0; it < BMv / 32; it++) {
        int id = it * 256 + tid;
        int r = id >> 3, c = id & 7;
        uint32_t dst = sbase + (uint32_t)(r * LDS_PAD + c * 8) * 2;
        cp_async16(dst, A + (size_t)(m0 + r) * ld2 + kA + c * 8, true);
    }
#pragma unroll
    for (int it = 0; it < 4; it++) {
        int id = it * 256 + tid;
        int r = id >> 3, c = id & 7;
        uint32_t dst = sbase + (uint32_t)(BMv * LDS_PAD + r * LDS_PAD + c * 8) * 2;
        bool ok = (n0 + r) < N;
        int gn = ok ? (n0 + r) : 0;
        cp_async16(dst, Bm + (size_t)gn * ld2 + kB + c * 8, ok);
    }
}

template <int BMv, int EPI>
__global__ __launch_bounds__(256, 2)
void gemm_wmma(const __nv_bfloat16* __restrict__ A,
               const __nv_bfloat16* __restrict__ Bm,
               float* __restrict__ C,
               int M, int N, int K) {
    constexpr int WM_CNT  = BMv / 32;          // warps along M (4 or 2)
    constexpr int WN_CNT  = 8 / WM_CNT;        // warps along N (2 or 4)
    constexpr int NJ      = (BN / WN_CNT) / 16;  // 4 or 2
    constexpr int STAGE_E = (BMv + BN) * LDS_PAD;
    constexpr int STAGE_B = STAGE_E * 2;

    extern __shared__ __nv_bfloat16 smem[];
    const uint32_t sm0 = (uint32_t)__cvta_generic_to_shared(smem);
    const int tid  = threadIdx.x;
    const int warp = tid >> 5, lane = tid & 31;
    const int wm = warp % WM_CNT;
    const int wn = warp / WM_CNT;
    const int m0 = blockIdx.y * BMv;
    const int n0 = blockIdx.x * BN;
    const int NK = (3 * K) / BK;

    wmma::fragment<wmma::accumulator, 16, 16, 16, float> acc[2][NJ];
#pragma unroll
    for (int i = 0; i < 2; i++)
#pragma unroll
        for (int j = 0; j < NJ; j++) wmma::fill_fragment(acc[i][j], 0.f);

#pragma unroll
    for (int s = 0; s < NSTAGE - 1; s++) {
        load_stage64<BMv>(sm0 + s * STAGE_B, A, Bm, m0, n0, N, K, s * BK, tid);
        CP_COMMIT();
    }

    for (int kt = 0; kt < NK; kt++) {
        CP_WAIT(1);
        __syncthreads();
        int cn = kt + NSTAGE - 1;
        if (cn < NK)
            load_stage64<BMv>(sm0 + (cn % NSTAGE) * STAGE_B, A, Bm, m0, n0, N, K,
                              cn * BK, tid);
        CP_COMMIT();

        const __nv_bfloat16* sA = smem + (size_t)(kt % NSTAGE) * STAGE_E;
        const __nv_bfloat16* sB = sA + BMv * LDS_PAD;
#pragma unroll
        for (int ks = 0; ks < 4; ks++) {
            wmma::fragment<wmma::matrix_a, 16, 16, 16, __nv_bfloat16, wmma::row_major> af[2];
            wmma::fragment<wmma::matrix_b, 16, 16, 16, __nv_bfloat16, wmma::col_major> bfr[NJ];
#pragma unroll
            for (int i = 0; i < 2; i++)
                wmma::load_matrix_sync(af[i], sA + (wm * 32 + i * 16) * LDS_PAD + ks * 16, LDS_PAD);
#pragma unroll
            for (int j = 0; j < NJ; j++)
                wmma::load_matrix_sync(bfr[j], sB + (wn * (16 * NJ) + j * 16) * LDS_PAD + ks * 16, LDS_PAD);
#pragma unroll
            for (int i = 0; i < 2; i++)
#pragma unroll
                for (int j = 0; j < NJ; j++)
                    wmma::mma_sync(acc[i][j], af[i], bfr[j], acc[i][j]);
        }
    }
    __syncthreads();

    // epilogue: per-warp smem bounce, fused op
    float* scr = reinterpret_cast<float*>(smem) + warp * 256;
#pragma unroll
    for (int i = 0; i < 2; i++) {
#pragma unroll
        for (int j = 0; j < NJ; j++) {
            wmma::store_matrix_sync(scr, acc[i][j], 16, wmma::mem_row_major);
            __syncwarp();
            int r0 = m0 + wm * 32 + i * 16;
            int c0 = n0 + wn * (16 * NJ) + j * 16;
#pragma unroll
            for (int e = lane; e < 256; e += 32) {
                int rr = e >> 4, cc = e & 15;
                int gc = c0 + cc;
                if (gc < N) {
                    size_t off = (size_t)(r0 + rr) * N + gc;
                    float v = scr[e];
                    if (EPI == EP_ADD)  v += C[off];
                    if (EPI == EP_TANH) v = 30.f * tanhf(v * (1.f / 30.f));
                    C[off] = v;
                }
            }
            __syncwarp();
        }
    }
}

// ===================== elementwise / attention kernels =====================
__global__ void embed_kernel(const int* __restrict__ idx, const float* __restrict__ tok) {
    int i = blockIdx.x * 256 + threadIdx.x;
    int bt = i >> 10;
    int e  = i & (E_ - 1);
    float v = tok[(size_t)idx[bt] * E_ + e];
    g_x[i]  = v;
    g_x0[i] = v;
}

__global__ void rmsnorm_split(const float* __restrict__ x, const float* __restrict__ w,
                              float* __restrict__ h, __nv_bfloat16* __restrict__ a2) {
    __shared__ float red[8];
    int row = blockIdx.x;
    int tid = threadIdx.x;
    const float4 xv = ((const float4*)(x + (size_t)row * E_))[tid];
    float s = xv.x*xv.x + xv.y*xv.y + xv.z*xv.z + xv.w*xv.w;
#pragma unroll
    for (int o = 16; o; o >>= 1) s += __shfl_xor_sync(0xFFFFFFFFu, s, o);
    if ((tid & 31) == 0) red[tid >> 5] = s;
    __syncthreads();
    if (tid == 0) {
        float t = 0.f;
#pragma unroll
        for (int i = 0; i < 8; i++) t += red[i];
        red[0] = rsqrtf(t * (1.f / E_) + 1e-6f);
    }
    __syncthreads();
    float norm = red[0];
    const float4 wv = ((const float4*)w)[tid];
    float v[4] = {xv.x*norm*wv.x, xv.y*norm*wv.y, xv.z*norm*wv.z, xv.w*norm*wv.w};
    if (h) ((float4*)(h + (size_t)row * E_))[tid] = make_float4(v[0], v[1], v[2], v[3]);
    union { __nv_bfloat162 b2[2]; uint2 u; } hi, lo;
#pragma unroll
    for (int j = 0; j < 2; j++) {
        __nv_bfloat16 h0 = __float2bfloat16(v[2*j]);
        __nv_bfloat16 h1 = __float2bfloat16(v[2*j+1]);
        hi.b2[j] = __nv_bfloat162(h0, h1);
        lo.b2[j] = __floats2bfloat162_rn(v[2*j] - __bfloat162float(h0),
                                         v[2*j+1] - __bfloat162float(h1));
    }
    __nv_bfloat16* dbase = a2 + (size_t)row * 2 * E_ + tid * 4;
    *((uint2*)dbase)        = hi.u;
    *((uint2*)(dbase + E_)) = lo.u;
}

__global__ void gate_kernel(const float* __restrict__ hn, const float* __restrict__ vgw) {
    int i = blockIdx.x * 256 + threadIdx.x;
    if (i >= M_ * H_) return;
    int bt = i / H_, h = i % H_;
    const float* hr = hn + (size_t)bt * E_;
    const float* wr = vgw + h * 32;
    float s = 0.f;
#pragma unroll
    for (int c = 0; c < 32; c++) s = fmaf(hr[c], wr[c], s);
    g_gate[i] = 2.f / (1.f + expf(-s));
}

__global__ void rope_split_kernel(const float* __restrict__ qkv, int has_gate) {
    int bt = blockIdx.x;
    int b = bt / T_, t = bt % T_;
    const float* src = qkv + (size_t)bt * 3 * E_;
    float tf = (float)t;
#pragma unroll
    for (int which = 0; which < 2; ++which) {
        const float* sp = src + which * E_;
        float* dst = (which == 0) ? g_q : g_k;
        for (int item = threadIdx.x; item < H_ * 32; item += blockDim.x) {
            int h = item >> 5, p = item & 31;
            int d0 = 2 * p, d1 = 2 * p + 1;
            float ang0 = tf * powf(10000.f, -(float)(d0 & 31) * (1.f / 32.f));
            float ang1 = tf * powf(10000.f, -(float)(d1 & 31) * (1.f / 32.f));
            float s0, c0, s1, c1;
            sincosf(ang0, &s0, &c0);
            sincosf(ang1, &s1, &c1);
            float x0v = sp[h * HD_ + d0];
            float x1v = sp[h * HD_ + d1];
            float o0 = x0v * c0 - x1v * s0;
            float o1 = x1v * c1 + x0v * s1;
            size_t base = ((size_t)(b * H_ + h) * T_ + t) * HD_;
            dst[base + d0] = o0;
            dst[base + d1] = o1;
        }
    }
    for (int item = threadIdx.x; item < E_; item += blockDim.x) {
        int h = item >> 6, d = item & 63;
        float vv = src[2 * E_ + item];
        if (has_gate)
            vv += g_gate[bt * H_ + h] * g_x0[(size_t)bt * E_ + item];
        g_v[((size_t)(b * H_ + h) * T_ + t) * HD_ + d] = vv;
    }
}

__global__ __launch_bounds__(128) void attn_kernel() {
    __shared__ float Ks[64][64];
    __shared__ float Vs[64][64];
    int bh = blockIdx.y;
    int qi = blockIdx.x * 128 + threadIdx.x;
    const float* qp = g_q + ((size_t)bh * T_ + qi) * HD_;

    float q[64], o[64];
#pragma unroll
    for (int d4 = 0; d4 < 16; d4++) {
        float4 v = ((const float4*)qp)[d4];
        q[4*d4] = v.x; q[4*d4+1] = v.y; q[4*d4+2] = v.z; q[4*d4+3] = v.w;
    }
#pragma unroll
    for (int d = 0; d < 64; d++) o[d] = 0.f;
    float m = -1e30f, l = 0.f;

    int ntiles = blockIdx.x * 2 + 2;
    for (int kt = 0; kt < ntiles; kt++) {
        const float* kp = g_k + ((size_t)bh * T_ + kt * 64) * HD_;
        const float* vp = g_v + ((size_t)bh * T_ + kt * 64) * HD_;
        __syncthreads();
        for (int f = threadIdx.x; f < 64 * 16; f += 128) {
            int r = f >> 4, c4 = f & 15;
            ((float4*)&Ks[r][0])[c4] = ((const float4*)(kp + r * 64))[c4];
            ((float4*)&Vs[r][0])[c4] = ((const float4*)(vp + r * 64))[c4];
        }
        __syncthreads();
        int jmax = qi - kt * 64 + 1;
        if (jmax > 64) jmax = 64;
        for (int j = 0; j < jmax; j++) {
            float s = 0.f;
            const float4* kr = (const float4*)&Ks[j][0];
#pragma unroll
            for (int d4 = 0; d4 < 16; d4++) {
                float4 kk = kr[d4];
                s = fmaf(q[4*d4],   kk.x, s);
                s = fmaf(q[4*d4+1], kk.y, s);
                s = fmaf(q[4*d4+2], kk.z, s);
                s = fmaf(q[4*d4+3], kk.w, s);
            }
            s *= 0.125f;
            float mn   = fmaxf(m, s);
            float corr = __expf(m - mn);
            float p    = __expf(s - mn);
            l = l * corr + p;
            m = mn;
            const float4* vr = (const float4*)&Vs[j][0];
#pragma unroll
            for (int d4 = 0; d4 < 16; d4++) {
                float4 vv = vr[d4];
                o[4*d4]   = fmaf(p, vv.x, o[4*d4]   * corr);
                o[4*d4+1] = fmaf(p, vv.y, o[4*d4+1] * corr);
                o[4*d4+2] = fmaf(p, vv.z, o[4*d4+2] * corr);
                o[4*d4+3] = fmaf(p, vv.w, o[4*d4+3] * corr);
            }
        }
    }
    float inv = 1.f / l;
    int b = bh / H_, h = bh % H_;
    __nv_bfloat16* hb = g_a2s + (size_t)(b * T_ + qi) * 2 * E_ + h * HD_;
#pragma unroll
    for (int d4 = 0; d4 < 16; d4++) {
        float v0 = o[4*d4]   * inv, v1 = o[4*d4+1] * inv;
        float v2 = o[4*d4+2] * inv, v3 = o[4*d4+3] * inv;
        __nv_bfloat16 h0 = __float2bfloat16(v0), h1 = __float2bfloat16(v1);
        __nv_bfloat16 h2 = __float2bfloat16(v2), h3 = __float2bfloat16(v3);
        union { __nv_bfloat162 b2[2]; uint2 u; } hi, lo;
        hi.b2[0] = __nv_bfloat162(h0, h1);
        hi.b2[1] = __nv_bfloat162(h2, h3);
        lo.b2[0] = __floats2bfloat162_rn(v0 - __bfloat162float(h0), v1 - __bfloat162float(h1));
        lo.b2[1] = __floats2bfloat162_rn(v2 - __bfloat162float(h2), v3 - __bfloat162float(h3));
        *((uint2*)(hb + d4 * 4))       = hi.u;
        *((uint2*)(hb + E_ + d4 * 4))  = lo.u;
    }
}

__global__ void swiglu_split() {
    size_t i4 = (size_t)blockIdx.x * 256 + threadIdx.x;
    size_t m = i4 / (FF_ / 4);
    int f4 = (int)(i4 - m * (FF_ / 4));
    const float* row = g_gu + m * (size_t)(2 * FF_);
    float4 g = ((const float4*)row)[f4];
    float4 u = ((const float4*)(row + FF_))[f4];
    float v[4];
    v[0] = (g.x / (1.f + expf(-g.x))) * u.x;
    v[1] = (g.y / (1.f + expf(-g.y))) * u.y;
    v[2] = (g.z / (1.f + expf(-g.z))) * u.z;
    v[3] = (g.w / (1.f + expf(-g.w))) * u.w;
    union { __nv_bfloat162 b2[2]; uint2 uu; } hi, lo;
#pragma unroll
    for (int j = 0; j < 2; j++) {
        __nv_bfloat16 h0 = __float2bfloat16(v[2*j]);
        __nv_bfloat16 h1 = __float2bfloat16(v[2*j+1]);
        hi.b2[j] = __nv_bfloat162(h0, h1);
        lo.b2[j] = __floats2bfloat162_rn(v[2*j] - __bfloat162float(h0),
                                         v[2*j+1] - __bfloat162float(h1));
    }
    __nv_bfloat16* dbase = g_a2b + m * (size_t)(2 * FF_) + f4 * 4;
    *((uint2*)dbase)         = hi.uu;
    *((uint2*)(dbase + FF_)) = lo.uu;
}

// ===================== host-side launchers =====================
template <int BMv, int EPI>
static void run_gemm(const __nv_bfloat16* A2, const __nv_bfloat16* B2, float* C,
                     int M, int N, int K) {
    constexpr size_t SMB = (size_t)NSTAGE * (BMv + BN) * LDS_PAD * 2;
    dim3 grid((N + BN - 1) / BN, M / BMv);
    gemm_wmma<BMv, EPI><<<grid, 256, SMB>>>(A2, B2, C, M, N, K);
}

static void run_cvt2(const float* src, __nv_bfloat16* dst, int K, long long rows,
                     int RPL, long long ostride, int ooff) {
    long long total8 = rows * K / 8;
    unsigned blocks = (unsigned)((total8 + 255) / 256);
    cvt2<<<blocks, 256>>>(src, dst, K, total8, RPL, ostride, ooff);
}

// ===================== launch =====================
extern "C" void kernel_launch(void* const* d_in, const int* in_sizes, int n_in,
                              void* d_out, int out_size) {
    const int*   idx  = (const int*)  d_in[0];
    const float* tok  = (const float*)d_in[1];
    const float* ln1  = (const float*)d_in[2];
    const float* qkvw = (const float*)d_in[3];
    const float* outw = (const float*)d_in[4];
    const float* vgw  = (const float*)d_in[5];
    const float* ln2  = (const float*)d_in[6];
    const float* wgw  = (const float*)d_in[7];
    const float* wuw  = (const float*)d_in[8];
    const float* wdw  = (const float*)d_in[9];
    const float* lnf  = (const float*)d_in[10];
    float* out = (float*)d_out;

    constexpr int SMB128 = NSTAGE * (128 + BN) * LDS_PAD * 2;  // 110592
    constexpr int SMB64  = NSTAGE * (64  + BN) * LDS_PAD * 2;  // 82944
    cudaFuncSetAttribute(gemm_wmma<128, EP_NONE>, cudaFuncAttributeMaxDynamicSharedMemorySize, SMB128);
    cudaFuncSetAttribute(gemm_wmma<128, EP_TANH>, cudaFuncAttributeMaxDynamicSharedMemorySize, SMB128);
    cudaFuncSetAttribute(gemm_wmma<64,  EP_ADD>,  cudaFuncAttributeMaxDynamicSharedMemorySize, SMB64);

    float *x, *h, *qkv, *gu;
    cudaGetSymbolAddress((void**)&x,   g_x);
    cudaGetSymbolAddress((void**)&h,   g_h);
    cudaGetSymbolAddress((void**)&qkv, g_qkv);
    cudaGetSymbolAddress((void**)&gu,  g_gu);

    __nv_bfloat16 *wqkv2, *wout2, *wgu2, *wd2, *tok2, *a2s, *a2b;
    cudaGetSymbolAddress((void**)&wqkv2, g_wqkv2);
    cudaGetSymbolAddress((void**)&wout2, g_wout2);
    cudaGetSymbolAddress((void**)&wgu2,  g_wgu2);
    cudaGetSymbolAddress((void**)&wd2,   g_wd2);
    cudaGetSymbolAddress((void**)&tok2,  g_tok2);
    cudaGetSymbolAddress((void**)&a2s,   g_a2s);
    cudaGetSymbolAddress((void**)&a2b,   g_a2b);

    // ---- weight split conversions ([hi|lo], vectorized) ----
    run_cvt2(qkvw, wqkv2, E_,  (long long)L_ * 3 * E_, 3 * E_,  3 * E_,  0);
    run_cvt2(outw, wout2, E_,  (long long)L_ * E_,     E_,      E_,      0);
    run_cvt2(wgw,  wgu2,  E_,  (long long)L_ * FF_,    FF_,     2 * FF_, 0);
    run_cvt2(wuw,  wgu2,  E_,  (long long)L_ * FF_,    FF_,     2 * FF_, FF_);
    run_cvt2(wdw,  wd2,   FF_, (long long)L_ * E_,     E_,      E_,      0);
    run_cvt2(tok,  tok2,  E_,  (long long)V_,          V_,      V_,      0);

    embed_kernel<<<(M_ * E_) / 256, 256>>>(idx, tok);

    for (int i = 0; i < L_; i++) {
        rmsnorm_split<<<M_, 256>>>(x, ln1 + i * E_, h, a2s);
        run_gemm<128, EP_NONE>(a2s, wqkv2 + (size_t)i * 3 * E_ * 2 * E_, qkv, M_, 3 * E_, E_);
        if (i & 1)
            gate_kernel<<<(M_ * H_ + 255) / 256, 256>>>(h, vgw + (size_t)i * H_ * 32);
        rope_split_kernel<<<M_, 256>>>(qkv, i & 1);
        attn_kernel<<<dim3(T_ / 128, B_ * H_), 128>>>();   // writes split into a2s
        run_gemm<64, EP_ADD>(a2s, wout2 + (size_t)i * E_ * 2 * E_, x, M_, E_, E_);

        rmsnorm_split<<<M_, 256>>>(x, ln2 + i * E_, nullptr, a2s);
        run_gemm<128, EP_NONE>(a2s, wgu2 + (size_t)i * 2 * FF_ * 2 * E_, gu, M_, 2 * FF_, E_);
        swiglu_split<<<(M_ * FF_ / 4) / 256, 256>>>();
        run_gemm<64, EP_ADD>(a2b, wd2 + (size_t)i * E_ * 2 * FF_, x, M_, E_, FF_);
    }

    rmsnorm_split<<<M_, 256>>>(x, lnf, nullptr, a2s);
    run_gemm<128, EP_TANH>(a2s, tok2, out, M_, V_, E_);
}